// round 1
// baseline (speedup 1.0000x reference)
#include <cuda_runtime.h>
#include <math.h>

#define B_ 8192
#define H_ 896
#define S_ 448
#define Q_ 256

// Scratch (allocation-free): R_u|R_r|R_e then t1|t2
__device__ float g_R[3u * B_ * H_];          // 88 MB
__device__ float g_t[2u * B_ * S_];          // 14.7 MB

#define BM 128
#define BN 128
#define BK 16
#define TM 8
#define TN 8

// C[M,N] = A[M,K] @ W[N,K]^T  (both K-major), optional bias / bias+relu
// EPI: 0 = none, 1 = +bias, 2 = relu(+bias)
template<int EPI>
__global__ __launch_bounds__(256, 2)
void gemm_tn(const float* __restrict__ A, int lda,
             const float* __restrict__ W, int N, int K,
             const float* __restrict__ bias,
             float* __restrict__ C, int ldc)
{
    __shared__ float As[BK][BM + 4];
    __shared__ float Ws[BK][BN + 4];

    const int t  = threadIdx.x;
    const int tx = t & 15;        // 16 cols of threads
    const int ty = t >> 4;        // 16 rows of threads
    const int m0 = blockIdx.y * BM;
    const int n0 = blockIdx.x * BN;

    float acc[TM][TN];
#pragma unroll
    for (int i = 0; i < TM; i++)
#pragma unroll
        for (int j = 0; j < TN; j++) acc[i][j] = 0.f;

    const int r0 = t >> 2;          // 0..63  (row within half-tile)
    const int c4 = (t & 3) * 4;     // 0,4,8,12 (k offset of float4)

    for (int k0 = 0; k0 < K; k0 += BK) {
        // ---- load A tile (BM x BK), transpose into As[k][m]
#pragma unroll
        for (int p = 0; p < 2; p++) {
            int row = r0 + p * 64;
            float4 v = *reinterpret_cast<const float4*>(
                A + (size_t)(m0 + row) * lda + k0 + c4);
            As[c4 + 0][row] = v.x; As[c4 + 1][row] = v.y;
            As[c4 + 2][row] = v.z; As[c4 + 3][row] = v.w;
        }
        // ---- load W tile (BN x BK), transpose into Ws[k][n] (masked on N)
#pragma unroll
        for (int p = 0; p < 2; p++) {
            int row = r0 + p * 64;
            int n   = n0 + row;
            float4 v = make_float4(0.f, 0.f, 0.f, 0.f);
            if (n < N)
                v = *reinterpret_cast<const float4*>(
                    W + (size_t)n * K + k0 + c4);
            Ws[c4 + 0][row] = v.x; Ws[c4 + 1][row] = v.y;
            Ws[c4 + 2][row] = v.z; Ws[c4 + 3][row] = v.w;
        }
        __syncthreads();

#pragma unroll
        for (int kk = 0; kk < BK; kk++) {
            float a[TM], b[TN];
            *(float4*)&a[0] = *(const float4*)&As[kk][ty * TM];
            *(float4*)&a[4] = *(const float4*)&As[kk][ty * TM + 4];
            *(float4*)&b[0] = *(const float4*)&Ws[kk][tx * TN];
            *(float4*)&b[4] = *(const float4*)&Ws[kk][tx * TN + 4];
#pragma unroll
            for (int i = 0; i < TM; i++)
#pragma unroll
                for (int j = 0; j < TN; j++)
                    acc[i][j] = fmaf(a[i], b[j], acc[i][j]);
        }
        __syncthreads();
    }

    // ---- epilogue (N % 8 == 0 for all shapes here, so 8-col groups are all-in or all-out)
    const int nbase = n0 + tx * TN;
    if (nbase < N) {
        float bv[TN];
#pragma unroll
        for (int j = 0; j < TN; j++) bv[j] = (EPI >= 1) ? bias[nbase + j] : 0.f;
#pragma unroll
        for (int i = 0; i < TM; i++) {
            int m = m0 + ty * TM + i;
            float4 o0, o1;
            float v[TN];
#pragma unroll
            for (int j = 0; j < TN; j++) {
                float x = acc[i][j] + bv[j];
                if (EPI == 2) x = fmaxf(x, 0.f);
                v[j] = x;
            }
            o0 = make_float4(v[0], v[1], v[2], v[3]);
            o1 = make_float4(v[4], v[5], v[6], v[7]);
            *reinterpret_cast<float4*>(C + (size_t)m * ldc + nbase)     = o0;
            *reinterpret_cast<float4*>(C + (size_t)m * ldc + nbase + 4) = o1;
        }
    }
}

// Fused gate: tiny input projections (K=2 / K=3) computed inline + GRU-style cell
__global__ void gate_kernel(const float* __restrict__ prev_y,
                            const float* __restrict__ prev_hidden,
                            const float* __restrict__ coarse,
                            const float* __restrict__ W_Ic,   // [3*S_, 2]
                            const float* __restrict__ W_If,   // [3*S_, 3]
                            const float* __restrict__ bias_u,
                            const float* __restrict__ bias_r,
                            const float* __restrict__ bias_e,
                            const float* __restrict__ Rbuf,
                            float* __restrict__ hidden_out)
{
    int idx = blockIdx.x * blockDim.x + threadIdx.x;
    if (idx >= B_ * H_) return;
    int b = idx / H_;
    int j = idx % H_;

    float py0 = prev_y[b * 2 + 0];
    float py1 = prev_y[b * 2 + 1];

    float Iu, Ir, Ie;
    if (j < S_) {
        Iu = py0 * W_Ic[(          j) * 2] + py1 * W_Ic[(          j) * 2 + 1];
        Ir = py0 * W_Ic[(S_     + j) * 2] + py1 * W_Ic[(S_     + j) * 2 + 1];
        Ie = py0 * W_Ic[(2 * S_ + j) * 2] + py1 * W_Ic[(2 * S_ + j) * 2 + 1];
    } else {
        int jj = j - S_;
        float cc = coarse[b];
        Iu = py0 * W_If[(          jj) * 3] + py1 * W_If[(          jj) * 3 + 1] + cc * W_If[(          jj) * 3 + 2];
        Ir = py0 * W_If[(S_     + jj) * 3] + py1 * W_If[(S_     + jj) * 3 + 1] + cc * W_If[(S_     + jj) * 3 + 2];
        Ie = py0 * W_If[(2 * S_ + jj) * 3] + py1 * W_If[(2 * S_ + jj) * 3 + 1] + cc * W_If[(2 * S_ + jj) * 3 + 2];
    }

    const size_t NBH = (size_t)B_ * H_;
    float Ru = Rbuf[idx];
    float Rr = Rbuf[NBH + idx];
    float Re = Rbuf[2 * NBH + idx];

    float u = 1.f / (1.f + expf(-(Ru + Iu + bias_u[j])));
    float r = 1.f / (1.f + expf(-(Rr + Ir + bias_r[j])));
    float e = tanhf(r * Re + Ie + bias_e[j]);

    hidden_out[idx] = u * prev_hidden[idx] + (1.f - u) * e;
}

extern "C" void kernel_launch(void* const* d_in, const int* in_sizes, int n_in,
                              void* d_out, int out_size)
{
    const float* prev_y      = (const float*)d_in[0];
    const float* prev_hidden = (const float*)d_in[1];
    const float* coarse      = (const float*)d_in[2];
    const float* W_Ru        = (const float*)d_in[3];
    const float* W_Rr        = (const float*)d_in[4];
    const float* W_Re        = (const float*)d_in[5];
    const float* W_Ic        = (const float*)d_in[6];
    const float* W_If        = (const float*)d_in[7];
    const float* W_O1        = (const float*)d_in[8];
    const float* b_O1        = (const float*)d_in[9];
    const float* W_O2        = (const float*)d_in[10];
    const float* b_O2        = (const float*)d_in[11];
    const float* W_O3        = (const float*)d_in[12];
    const float* b_O3        = (const float*)d_in[13];
    const float* W_O4        = (const float*)d_in[14];
    const float* b_O4        = (const float*)d_in[15];
    const float* bias_u      = (const float*)d_in[16];
    const float* bias_r      = (const float*)d_in[17];
    const float* bias_e      = (const float*)d_in[18];

    float* out        = (float*)d_out;
    float* out_coarse = out;
    float* out_fine   = out + (size_t)B_ * Q_;
    float* hidden     = out + 2 * (size_t)B_ * Q_;

    float* Rbuf = nullptr;
    float* Tbuf = nullptr;
    cudaGetSymbolAddress((void**)&Rbuf, g_R);
    cudaGetSymbolAddress((void**)&Tbuf, g_t);
    const size_t NBH = (size_t)B_ * H_;
    const size_t NBS = (size_t)B_ * S_;

    dim3 blk(256);

    // 1) recurrent projections: [8192,896] x [896,896]^T  (x3)
    dim3 g1(H_ / BN, B_ / BM);  // (7, 64)
    gemm_tn<0><<<g1, blk>>>(prev_hidden, H_, W_Ru, H_, H_, nullptr, Rbuf,           H_);
    gemm_tn<0><<<g1, blk>>>(prev_hidden, H_, W_Rr, H_, H_, nullptr, Rbuf + NBH,     H_);
    gemm_tn<0><<<g1, blk>>>(prev_hidden, H_, W_Re, H_, H_, nullptr, Rbuf + 2 * NBH, H_);

    // 2) fused gates -> hidden (written directly into d_out)
    gate_kernel<<<(B_ * H_) / 256, 256>>>(prev_y, prev_hidden, coarse, W_Ic, W_If,
                                          bias_u, bias_r, bias_e, Rbuf, hidden);

    // 3) first output MLP layers: relu(h_half @ W^T + b), strided A reads from hidden
    dim3 g2((S_ + BN - 1) / BN, B_ / BM);  // (4, 64)
    gemm_tn<2><<<g2, blk>>>(hidden,      H_, W_O1, S_, S_, b_O1, Tbuf,       S_);
    gemm_tn<2><<<g2, blk>>>(hidden + S_, H_, W_O3, S_, S_, b_O3, Tbuf + NBS, S_);

    // 4) second output MLP layers -> out_coarse / out_fine
    dim3 g3(Q_ / BN, B_ / BM);  // (2, 64)
    gemm_tn<1><<<g3, blk>>>(Tbuf,       S_, W_O2, Q_, S_, b_O2, out_coarse, Q_);
    gemm_tn<1><<<g3, blk>>>(Tbuf + NBS, S_, W_O4, Q_, S_, b_O4, out_fine,   Q_);
}

// round 3
// speedup vs baseline: 2.7725x; 2.7725x over previous
#include <cuda_runtime.h>
#include <cuda_bf16.h>
#include <math.h>
#include <stdint.h>

#define B_ 8192
#define H_ 896
#define S_ 448
#define Q_ 256

// ---------------- scratch (allocation-free __device__ globals) ----------------
__device__ float g_R[3ull * B_ * H_];                    // R_u | R_r | R_e
__device__ __nv_bfloat16 g_Ah[(size_t)B_ * H_];
__device__ __nv_bfloat16 g_Al[(size_t)B_ * H_];
__device__ __nv_bfloat16 g_Hh[(size_t)B_ * H_];
__device__ __nv_bfloat16 g_Hl[(size_t)B_ * H_];
__device__ __nv_bfloat16 g_Th[2ull * B_ * S_];
__device__ __nv_bfloat16 g_Tl[2ull * B_ * S_];
#define WSZ (3 * H_ * H_ + 2 * S_ * S_ + 2 * Q_ * S_)
__device__ __nv_bfloat16 g_Wh[WSZ];
__device__ __nv_bfloat16 g_Wl[WSZ];

#define OFF_WRU 0
#define OFF_WRR (H_ * H_)
#define OFF_WRE (2 * H_ * H_)
#define OFF_WO1 (3 * H_ * H_)
#define OFF_WO3 (3 * H_ * H_ + S_ * S_)
#define OFF_WO2 (3 * H_ * H_ + 2 * S_ * S_)
#define OFF_WO4 (3 * H_ * H_ + 2 * S_ * S_ + Q_ * S_)

// ---------------- PTX helpers (base sm_80+ features only) ----------------
__device__ __forceinline__ uint32_t s2u(const void* p) {
    return (uint32_t)__cvta_generic_to_shared(p);
}
__device__ __forceinline__ void cp_async16(uint32_t dst, const void* src, uint32_t bytes) {
    asm volatile("cp.async.cg.shared.global [%0], [%1], 16, %2;"
                 :: "r"(dst), "l"(src), "r"(bytes) : "memory");
}
__device__ __forceinline__ void cp_commit() {
    asm volatile("cp.async.commit_group;" ::: "memory");
}
template<int NN>
__device__ __forceinline__ void cp_wait() {
    asm volatile("cp.async.wait_group %0;" :: "n"(NN) : "memory");
}
__device__ __forceinline__ void ldm_x4(uint32_t* r, uint32_t addr) {
    asm volatile("ldmatrix.sync.aligned.m8n8.x4.shared.b16 {%0,%1,%2,%3}, [%4];"
                 : "=r"(r[0]), "=r"(r[1]), "=r"(r[2]), "=r"(r[3]) : "r"(addr));
}
__device__ __forceinline__ void mma_bf16(float* d, const uint32_t* a, uint32_t b0, uint32_t b1) {
    asm volatile("mma.sync.aligned.m16n8k16.row.col.f32.bf16.bf16.f32 "
                 "{%0,%1,%2,%3}, {%4,%5,%6,%7}, {%8,%9}, {%0,%1,%2,%3};"
                 : "+f"(d[0]), "+f"(d[1]), "+f"(d[2]), "+f"(d[3])
                 : "r"(a[0]), "r"(a[1]), "r"(a[2]), "r"(a[3]), "r"(b0), "r"(b1));
}

// ---------------- GEMM: C[M,N] = (Ah+Al)[M,K] @ (Wh+Wl)[N,K]^T ----------------
// smem stage: Ah(8K) | Al(8K) | Wh(8K) | Wl(8K) = 32KB, double-buffered.
// EPI: 0 = fp32, 1 = +bias fp32, 2 = relu(+bias) -> bf16 hi/lo pair
#define STAGE_BYTES 32768
#define SMEM_TOTAL (2 * STAGE_BYTES)

template<int EPI>
__global__ __launch_bounds__(256, 2)
void gemm_mma(const __nv_bfloat16* __restrict__ Ah, const __nv_bfloat16* __restrict__ Al, int lda,
              const __nv_bfloat16* __restrict__ Wh, const __nv_bfloat16* __restrict__ Wl,
              int N, int K, const float* __restrict__ bias,
              float* __restrict__ Cf, __nv_bfloat16* __restrict__ Chi,
              __nv_bfloat16* __restrict__ Clo, int ldc)
{
    extern __shared__ char smem[];
    const int t  = threadIdx.x;
    const int m0 = blockIdx.y * 128;
    const int n0 = blockIdx.x * 128;
    const int tile_n = min(128, N - n0);
    const uint32_t sb0 = s2u(smem);
    const int lane = t & 31;
    const int wid  = t >> 5;
    const int wm = (wid & 3) * 32;   // warp row base within tile
    const int wn = (wid >> 2) * 64;  // warp col base within tile

    float acc[2][8][4];
#pragma unroll
    for (int a = 0; a < 2; a++)
#pragma unroll
        for (int b = 0; b < 8; b++)
#pragma unroll
            for (int d = 0; d < 4; d++) acc[a][b][d] = 0.f;

    const int nch = K / 32;

    auto load_stage = [&](int c, int st) {
        const int k0 = c * 32;
        const uint32_t sb = sb0 + st * STAGE_BYTES;
#pragma unroll
        for (int i = 0; i < 8; ++i) {
            const int tile   = i >> 1;
            const int within = t + (i & 1) * 256;   // 0..511
            const int row    = within >> 2;         // 0..127
            const int ch     = within & 3;          // 16B chunk in 64B row
            const uint32_t dst = sb + tile * 8192 + row * 64 +
                                 ((ch ^ ((row >> 1) & 3)) * 16);
            if (tile < 2) {
                const __nv_bfloat16* base = (tile == 0) ? Ah : Al;
                cp_async16(dst, base + (size_t)(m0 + row) * lda + k0 + ch * 8, 16);
            } else {
                const __nv_bfloat16* base = (tile == 2) ? Wh : Wl;
                const int r = (row < tile_n) ? row : (tile_n - 1);
                cp_async16(dst, base + (size_t)(n0 + r) * K + k0 + ch * 8,
                           (row < tile_n) ? 16u : 0u);
            }
        }
        cp_commit();
    };

    load_stage(0, 0);

    // ldmatrix per-lane source rows/chunks
    const int arow = (lane & 7) + ((lane >> 3) & 1) * 8;   // A: m within 16-tile
    const int asel = (lane >> 4) & 1;                       // A: k-chunk select
    const int brow = (lane & 7) + ((lane >> 4) & 1) * 8;   // B: n within 16
    const int bsel = (lane >> 3) & 1;                       // B: k-chunk select

    for (int c = 0; c < nch; ++c) {
        if (c + 1 < nch) { load_stage(c + 1, (c + 1) & 1); cp_wait<1>(); }
        else             { cp_wait<0>(); }
        __syncthreads();
        const uint32_t sb = sb0 + (c & 1) * STAGE_BYTES;
#pragma unroll
        for (int ks = 0; ks < 2; ++ks) {
            uint32_t ahf[2][4], alf[2][4];
            const int ach = ks * 2 + asel;
#pragma unroll
            for (int mt = 0; mt < 2; ++mt) {
                const int row = wm + mt * 16 + arow;
                const uint32_t ad = sb + row * 64 + ((ach ^ ((row >> 1) & 3)) * 16);
                ldm_x4(ahf[mt], ad);
                ldm_x4(alf[mt], ad + 8192);
            }
            const int bch = ks * 2 + bsel;
#pragma unroll
            for (int hb = 0; hb < 2; ++hb) {
                uint32_t bhf[2][4], blf[2][4];
#pragma unroll
                for (int p = 0; p < 2; ++p) {
                    const int nrow = wn + hb * 32 + p * 16 + brow;
                    const uint32_t bd = sb + 16384 + nrow * 64 +
                                        ((bch ^ ((nrow >> 1) & 3)) * 16);
                    ldm_x4(bhf[p], bd);
                    ldm_x4(blf[p], bd + 8192);
                }
                // term Ah*Wh
#pragma unroll
                for (int mt = 0; mt < 2; ++mt)
#pragma unroll
                    for (int q = 0; q < 4; ++q)
                        mma_bf16(acc[mt][hb * 4 + q], ahf[mt],
                                 bhf[q >> 1][(q & 1) * 2], bhf[q >> 1][(q & 1) * 2 + 1]);
                // term Ah*Wl
#pragma unroll
                for (int mt = 0; mt < 2; ++mt)
#pragma unroll
                    for (int q = 0; q < 4; ++q)
                        mma_bf16(acc[mt][hb * 4 + q], ahf[mt],
                                 blf[q >> 1][(q & 1) * 2], blf[q >> 1][(q & 1) * 2 + 1]);
                // term Al*Wh
#pragma unroll
                for (int mt = 0; mt < 2; ++mt)
#pragma unroll
                    for (int q = 0; q < 4; ++q)
                        mma_bf16(acc[mt][hb * 4 + q], alf[mt],
                                 bhf[q >> 1][(q & 1) * 2], bhf[q >> 1][(q & 1) * 2 + 1]);
            }
        }
        __syncthreads();
    }

    // ---- epilogue
    const int gid = lane >> 2;
    const int cp2 = (lane & 3) * 2;
#pragma unroll
    for (int mt = 0; mt < 2; ++mt) {
        const int r0 = m0 + wm + mt * 16 + gid;
#pragma unroll
        for (int nt = 0; nt < 8; ++nt) {
            const int col = n0 + wn + nt * 8 + cp2;
            if (col < N) {
                float x0 = acc[mt][nt][0], x1 = acc[mt][nt][1];
                float x2 = acc[mt][nt][2], x3 = acc[mt][nt][3];
                if (EPI >= 1) {
                    const float bb0 = bias[col], bb1 = bias[col + 1];
                    x0 += bb0; x1 += bb1; x2 += bb0; x3 += bb1;
                }
                if (EPI == 2) {
                    x0 = fmaxf(x0, 0.f); x1 = fmaxf(x1, 0.f);
                    x2 = fmaxf(x2, 0.f); x3 = fmaxf(x3, 0.f);
                    __nv_bfloat16 h0 = __float2bfloat16(x0), h1 = __float2bfloat16(x1);
                    __nv_bfloat16 h2 = __float2bfloat16(x2), h3 = __float2bfloat16(x3);
                    __nv_bfloat16 l0 = __float2bfloat16(x0 - __bfloat162float(h0));
                    __nv_bfloat16 l1 = __float2bfloat16(x1 - __bfloat162float(h1));
                    __nv_bfloat16 l2 = __float2bfloat16(x2 - __bfloat162float(h2));
                    __nv_bfloat16 l3 = __float2bfloat16(x3 - __bfloat162float(h3));
                    *(__nv_bfloat162*)(Chi + (size_t)r0 * ldc + col)       = __nv_bfloat162(h0, h1);
                    *(__nv_bfloat162*)(Chi + (size_t)(r0 + 8) * ldc + col) = __nv_bfloat162(h2, h3);
                    *(__nv_bfloat162*)(Clo + (size_t)r0 * ldc + col)       = __nv_bfloat162(l0, l1);
                    *(__nv_bfloat162*)(Clo + (size_t)(r0 + 8) * ldc + col) = __nv_bfloat162(l2, l3);
                } else {
                    *(float2*)(Cf + (size_t)r0 * ldc + col)       = make_float2(x0, x1);
                    *(float2*)(Cf + (size_t)(r0 + 8) * ldc + col) = make_float2(x2, x3);
                }
            }
        }
    }
}

// ---------------- fp32 -> bf16 hi/lo split ----------------
__global__ void cvt_kernel(const float* __restrict__ src,
                           __nv_bfloat16* __restrict__ hi,
                           __nv_bfloat16* __restrict__ lo, int n)
{
    int i = blockIdx.x * blockDim.x + threadIdx.x;
    if (i < n) {
        float x = src[i];
        __nv_bfloat16 h = __float2bfloat16(x);
        hi[i] = h;
        lo[i] = __float2bfloat16(x - __bfloat162float(h));
    }
}

// ---------------- fused gate (vectorized x4) ----------------
__global__ void gate_kernel(const float* __restrict__ prev_y,
                            const float* __restrict__ prev_hidden,
                            const float* __restrict__ coarse,
                            const float* __restrict__ W_Ic,
                            const float* __restrict__ W_If,
                            const float* __restrict__ bias_u,
                            const float* __restrict__ bias_r,
                            const float* __restrict__ bias_e,
                            const float* __restrict__ Rbuf,
                            float* __restrict__ hidden_out,
                            __nv_bfloat16* __restrict__ hid_hi,
                            __nv_bfloat16* __restrict__ hid_lo)
{
    const int HV = H_ / 4;  // 224
    int v = blockIdx.x * blockDim.x + threadIdx.x;
    if (v >= B_ * HV) return;
    int b = v / HV;
    int j = (v - b * HV) * 4;
    size_t idx = (size_t)b * H_ + j;
    const size_t NBH = (size_t)B_ * H_;

    float py0 = prev_y[2 * b], py1 = prev_y[2 * b + 1];
    float4 Ru4 = *(const float4*)(Rbuf + idx);
    float4 Rr4 = *(const float4*)(Rbuf + NBH + idx);
    float4 Re4 = *(const float4*)(Rbuf + 2 * NBH + idx);
    float4 ph4 = *(const float4*)(prev_hidden + idx);

    float h[4];
    const float* Ru = (const float*)&Ru4;
    const float* Rr = (const float*)&Rr4;
    const float* Re = (const float*)&Re4;
    const float* ph = (const float*)&ph4;

    if (j < S_) {
#pragma unroll
        for (int q = 0; q < 4; ++q) {
            int jj = j + q;
            float Iu = py0 * W_Ic[jj * 2] + py1 * W_Ic[jj * 2 + 1];
            float Ir = py0 * W_Ic[(S_ + jj) * 2] + py1 * W_Ic[(S_ + jj) * 2 + 1];
            float Ie = py0 * W_Ic[(2 * S_ + jj) * 2] + py1 * W_Ic[(2 * S_ + jj) * 2 + 1];
            float u = 1.f / (1.f + expf(-(Ru[q] + Iu + bias_u[jj])));
            float r = 1.f / (1.f + expf(-(Rr[q] + Ir + bias_r[jj])));
            float e = tanhf(r * Re[q] + Ie + bias_e[jj]);
            h[q] = u * ph[q] + (1.f - u) * e;
        }
    } else {
        float cc = coarse[b];
#pragma unroll
        for (int q = 0; q < 4; ++q) {
            int jj = j + q;
            int jf = jj - S_;
            float Iu = py0 * W_If[jf * 3] + py1 * W_If[jf * 3 + 1] + cc * W_If[jf * 3 + 2];
            float Ir = py0 * W_If[(S_ + jf) * 3] + py1 * W_If[(S_ + jf) * 3 + 1] + cc * W_If[(S_ + jf) * 3 + 2];
            float Ie = py0 * W_If[(2 * S_ + jf) * 3] + py1 * W_If[(2 * S_ + jf) * 3 + 1] + cc * W_If[(2 * S_ + jf) * 3 + 2];
            float u = 1.f / (1.f + expf(-(Ru[q] + Iu + bias_u[jj])));
            float r = 1.f / (1.f + expf(-(Rr[q] + Ir + bias_r[jj])));
            float e = tanhf(r * Re[q] + Ie + bias_e[jj]);
            h[q] = u * ph[q] + (1.f - u) * e;
        }
    }

    *(float4*)(hidden_out + idx) = make_float4(h[0], h[1], h[2], h[3]);

    __nv_bfloat16 hh[4], hl[4];
#pragma unroll
    for (int q = 0; q < 4; ++q) {
        __nv_bfloat16 hi = __float2bfloat16(h[q]);
        hh[q] = hi;
        hl[q] = __float2bfloat16(h[q] - __bfloat162float(hi));
    }
    *(uint2*)(hid_hi + idx) = *(uint2*)hh;
    *(uint2*)(hid_lo + idx) = *(uint2*)hl;
}

// ---------------- launch ----------------
extern "C" void kernel_launch(void* const* d_in, const int* in_sizes, int n_in,
                              void* d_out, int out_size)
{
    const float* prev_y      = (const float*)d_in[0];
    const float* prev_hidden = (const float*)d_in[1];
    const float* coarse      = (const float*)d_in[2];
    const float* W_Ru        = (const float*)d_in[3];
    const float* W_Rr        = (const float*)d_in[4];
    const float* W_Re        = (const float*)d_in[5];
    const float* W_Ic        = (const float*)d_in[6];
    const float* W_If        = (const float*)d_in[7];
    const float* W_O1        = (const float*)d_in[8];
    const float* b_O1        = (const float*)d_in[9];
    const float* W_O2        = (const float*)d_in[10];
    const float* b_O2        = (const float*)d_in[11];
    const float* W_O3        = (const float*)d_in[12];
    const float* b_O3        = (const float*)d_in[13];
    const float* W_O4        = (const float*)d_in[14];
    const float* b_O4        = (const float*)d_in[15];
    const float* bias_u      = (const float*)d_in[16];
    const float* bias_r      = (const float*)d_in[17];
    const float* bias_e      = (const float*)d_in[18];

    float* out        = (float*)d_out;
    float* out_coarse = out;
    float* out_fine   = out + (size_t)B_ * Q_;
    float* hidden     = out + 2 * (size_t)B_ * Q_;

    float* Rbuf; __nv_bfloat16 *Ah, *Al, *Hh, *Hl, *Th, *Tl, *Wh, *Wl;
    cudaGetSymbolAddress((void**)&Rbuf, g_R);
    cudaGetSymbolAddress((void**)&Ah, g_Ah);
    cudaGetSymbolAddress((void**)&Al, g_Al);
    cudaGetSymbolAddress((void**)&Hh, g_Hh);
    cudaGetSymbolAddress((void**)&Hl, g_Hl);
    cudaGetSymbolAddress((void**)&Th, g_Th);
    cudaGetSymbolAddress((void**)&Tl, g_Tl);
    cudaGetSymbolAddress((void**)&Wh, g_Wh);
    cudaGetSymbolAddress((void**)&Wl, g_Wl);

    cudaFuncSetAttribute(gemm_mma<0>, cudaFuncAttributeMaxDynamicSharedMemorySize, SMEM_TOTAL);
    cudaFuncSetAttribute(gemm_mma<1>, cudaFuncAttributeMaxDynamicSharedMemorySize, SMEM_TOTAL);
    cudaFuncSetAttribute(gemm_mma<2>, cudaFuncAttributeMaxDynamicSharedMemorySize, SMEM_TOTAL);

    const size_t NBH = (size_t)B_ * H_;
    const size_t NBS = (size_t)B_ * S_;

    auto cvt = [&](const float* s, __nv_bfloat16* h, __nv_bfloat16* l, int n) {
        cvt_kernel<<<(n + 255) / 256, 256>>>(s, h, l, n);
    };
    cvt(prev_hidden, Ah, Al, B_ * H_);
    cvt(W_Ru, Wh + OFF_WRU, Wl + OFF_WRU, H_ * H_);
    cvt(W_Rr, Wh + OFF_WRR, Wl + OFF_WRR, H_ * H_);
    cvt(W_Re, Wh + OFF_WRE, Wl + OFF_WRE, H_ * H_);
    cvt(W_O1, Wh + OFF_WO1, Wl + OFF_WO1, S_ * S_);
    cvt(W_O3, Wh + OFF_WO3, Wl + OFF_WO3, S_ * S_);
    cvt(W_O2, Wh + OFF_WO2, Wl + OFF_WO2, Q_ * S_);
    cvt(W_O4, Wh + OFF_WO4, Wl + OFF_WO4, Q_ * S_);

    dim3 blk(256);

    // 1) recurrent projections -> g_R (fp32)
    dim3 g1(H_ / 128, B_ / 128);  // (7, 64)
    gemm_mma<0><<<g1, blk, SMEM_TOTAL>>>(Ah, Al, H_, Wh + OFF_WRU, Wl + OFF_WRU, H_, H_,
                                         nullptr, Rbuf, nullptr, nullptr, H_);
    gemm_mma<0><<<g1, blk, SMEM_TOTAL>>>(Ah, Al, H_, Wh + OFF_WRR, Wl + OFF_WRR, H_, H_,
                                         nullptr, Rbuf + NBH, nullptr, nullptr, H_);
    gemm_mma<0><<<g1, blk, SMEM_TOTAL>>>(Ah, Al, H_, Wh + OFF_WRE, Wl + OFF_WRE, H_, H_,
                                         nullptr, Rbuf + 2 * NBH, nullptr, nullptr, H_);

    // 2) fused gates -> hidden (fp32 to d_out) + bf16 hi/lo pair
    gate_kernel<<<(B_ * (H_ / 4) + 255) / 256, 256>>>(prev_y, prev_hidden, coarse, W_Ic, W_If,
                                                      bias_u, bias_r, bias_e, Rbuf, hidden, Hh, Hl);

    // 3) relu(h_half @ W^T + b) -> bf16 pair scratch
    dim3 g2((S_ + 127) / 128, B_ / 128);  // (4, 64)
    gemm_mma<2><<<g2, blk, SMEM_TOTAL>>>(Hh, Hl, H_, Wh + OFF_WO1, Wl + OFF_WO1, S_, S_,
                                         b_O1, nullptr, Th, Tl, S_);
    gemm_mma<2><<<g2, blk, SMEM_TOTAL>>>(Hh + S_, Hl + S_, H_, Wh + OFF_WO3, Wl + OFF_WO3, S_, S_,
                                         b_O3, nullptr, Th + NBS, Tl + NBS, S_);

    // 4) logits -> d_out
    dim3 g3(Q_ / 128, B_ / 128);  // (2, 64)
    gemm_mma<1><<<g3, blk, SMEM_TOTAL>>>(Th, Tl, S_, Wh + OFF_WO2, Wl + OFF_WO2, Q_, S_,
                                         b_O2, out_coarse, nullptr, nullptr, Q_);
    gemm_mma<1><<<g3, blk, SMEM_TOTAL>>>(Th + NBS, Tl + NBS, S_, Wh + OFF_WO4, Wl + OFF_WO4, Q_, S_,
                                         b_O4, out_fine, nullptr, nullptr, Q_);
}

// round 4
// speedup vs baseline: 2.9761x; 1.0734x over previous
#include <cuda_runtime.h>
#include <cuda_bf16.h>
#include <math.h>
#include <stdint.h>

#define B_ 8192
#define H_ 896
#define S_ 448
#define Q_ 256

// ---------------- scratch (allocation-free __device__ globals) ----------------
__device__ float g_R[3ull * B_ * H_];                    // R_u | R_r | R_e
__device__ __nv_bfloat16 g_Ah[(size_t)B_ * H_];
__device__ __nv_bfloat16 g_Al[(size_t)B_ * H_];
__device__ __nv_bfloat16 g_Hh[(size_t)B_ * H_];
__device__ __nv_bfloat16 g_Hl[(size_t)B_ * H_];
__device__ __nv_bfloat16 g_Th[2ull * B_ * S_];
__device__ __nv_bfloat16 g_Tl[2ull * B_ * S_];
#define WSZ (3 * H_ * H_ + 2 * S_ * S_ + 2 * Q_ * S_)
__device__ __nv_bfloat16 g_Wh[WSZ];
__device__ __nv_bfloat16 g_Wl[WSZ];

#define OFF_WR  0
#define OFF_WO1 (3 * H_ * H_)
#define OFF_WO3 (3 * H_ * H_ + S_ * S_)
#define OFF_WO2 (3 * H_ * H_ + 2 * S_ * S_)
#define OFF_WO4 (3 * H_ * H_ + 2 * S_ * S_ + Q_ * S_)

// ---------------- PTX helpers (base sm_80+ features only) ----------------
__device__ __forceinline__ uint32_t s2u(const void* p) {
    return (uint32_t)__cvta_generic_to_shared(p);
}
__device__ __forceinline__ void cp_async16(uint32_t dst, const void* src, uint32_t bytes) {
    asm volatile("cp.async.cg.shared.global [%0], [%1], 16, %2;"
                 :: "r"(dst), "l"(src), "r"(bytes) : "memory");
}
__device__ __forceinline__ void cp_commit() {
    asm volatile("cp.async.commit_group;" ::: "memory");
}
template<int NN>
__device__ __forceinline__ void cp_wait() {
    asm volatile("cp.async.wait_group %0;" :: "n"(NN) : "memory");
}
__device__ __forceinline__ void ldm_x4(uint32_t* r, uint32_t addr) {
    asm volatile("ldmatrix.sync.aligned.m8n8.x4.shared.b16 {%0,%1,%2,%3}, [%4];"
                 : "=r"(r[0]), "=r"(r[1]), "=r"(r[2]), "=r"(r[3]) : "r"(addr));
}
__device__ __forceinline__ void mma_bf16(float* d, const uint32_t* a, uint32_t b0, uint32_t b1) {
    asm volatile("mma.sync.aligned.m16n8k16.row.col.f32.bf16.bf16.f32 "
                 "{%0,%1,%2,%3}, {%4,%5,%6,%7}, {%8,%9}, {%0,%1,%2,%3};"
                 : "+f"(d[0]), "+f"(d[1]), "+f"(d[2]), "+f"(d[3])
                 : "r"(a[0]), "r"(a[1]), "r"(a[2]), "r"(a[3]), "r"(b0), "r"(b1));
}
__device__ __forceinline__ float ftanh(float x) {
    float y; asm("tanh.approx.f32 %0, %1;" : "=f"(y) : "f"(x)); return y;
}
__device__ __forceinline__ float fsigm(float x) {
    return 1.0f / (1.0f + __expf(-x));
}

// ---------------- GEMM: C[M,N] = (Ah+Al)[M,K] @ (Wh+Wl)[N,K]^T ----------------
// 128x128x32 tiles, 3-stage cp.async pipeline, 3-term bf16 split (fp32 accum).
// EPI: 0 = fp32, 1 = +bias fp32, 2 = relu(+bias) -> bf16 hi/lo pair
// SPLITC: columns are [gate*H_ + j]; store to Cf + gate*B_*H_ (all tiles full).
#define STAGE_BYTES 32768
#define NSTAGE 3
#define SMEM_TOTAL (NSTAGE * STAGE_BYTES)

template<int EPI, bool SPLITC>
__global__ __launch_bounds__(256, 2)
void gemm_mma(const __nv_bfloat16* __restrict__ Ah, const __nv_bfloat16* __restrict__ Al, int lda,
              const __nv_bfloat16* __restrict__ Wh, const __nv_bfloat16* __restrict__ Wl,
              int N, int K, const float* __restrict__ bias,
              float* __restrict__ Cf, __nv_bfloat16* __restrict__ Chi,
              __nv_bfloat16* __restrict__ Clo, int ldc)
{
    extern __shared__ char smem[];
    const int t  = threadIdx.x;
    const int m0 = blockIdx.y * 128;
    const int n0 = blockIdx.x * 128;
    const int tile_n = SPLITC ? 128 : min(128, N - n0);
    const uint32_t sb0 = s2u(smem);
    const int lane = t & 31;
    const int wid  = t >> 5;
    const int wm = (wid & 3) * 32;
    const int wn = (wid >> 2) * 64;

    float acc[2][8][4];
#pragma unroll
    for (int a = 0; a < 2; a++)
#pragma unroll
        for (int b = 0; b < 8; b++)
#pragma unroll
            for (int d = 0; d < 4; d++) acc[a][b][d] = 0.f;

    const int nch = K / 32;

    auto load_stage = [&](int c, int st) {
        const int k0 = c * 32;
        const uint32_t sb = sb0 + st * STAGE_BYTES;
#pragma unroll
        for (int i = 0; i < 8; ++i) {
            const int tile   = i >> 1;
            const int within = t + (i & 1) * 256;   // 0..511
            const int row    = within >> 2;
            const int ch     = within & 3;
            const uint32_t dst = sb + tile * 8192 + row * 64 +
                                 ((ch ^ ((row >> 1) & 3)) * 16);
            if (tile < 2) {
                const __nv_bfloat16* base = (tile == 0) ? Ah : Al;
                cp_async16(dst, base + (size_t)(m0 + row) * lda + k0 + ch * 8, 16);
            } else {
                const __nv_bfloat16* base = (tile == 2) ? Wh : Wl;
                const int r = (row < tile_n) ? row : (tile_n - 1);
                cp_async16(dst, base + (size_t)(n0 + r) * K + k0 + ch * 8,
                           (row < tile_n) ? 16u : 0u);
            }
        }
        cp_commit();
    };

    load_stage(0, 0);
    if (nch > 1) load_stage(1, 1);

    const int arow = (lane & 7) + ((lane >> 3) & 1) * 8;
    const int asel = (lane >> 4) & 1;
    const int brow = (lane & 7) + ((lane >> 4) & 1) * 8;
    const int bsel = (lane >> 3) & 1;

    for (int c = 0; c < nch; ++c) {
        if (c + 2 < nch) { load_stage(c + 2, (c + 2) % NSTAGE); cp_wait<2>(); }
        else if (c + 1 < nch) { cp_wait<1>(); }
        else { cp_wait<0>(); }
        __syncthreads();
        const uint32_t sb = sb0 + (c % NSTAGE) * STAGE_BYTES;
#pragma unroll
        for (int ks = 0; ks < 2; ++ks) {
            uint32_t ahf[2][4], alf[2][4];
            const int ach = ks * 2 + asel;
#pragma unroll
            for (int mt = 0; mt < 2; ++mt) {
                const int row = wm + mt * 16 + arow;
                const uint32_t ad = sb + row * 64 + ((ach ^ ((row >> 1) & 3)) * 16);
                ldm_x4(ahf[mt], ad);
                ldm_x4(alf[mt], ad + 8192);
            }
            const int bch = ks * 2 + bsel;
#pragma unroll
            for (int hb = 0; hb < 2; ++hb) {
                uint32_t bhf[2][4], blf[2][4];
#pragma unroll
                for (int p = 0; p < 2; ++p) {
                    const int nrow = wn + hb * 32 + p * 16 + brow;
                    const uint32_t bd = sb + 16384 + nrow * 64 +
                                        ((bch ^ ((nrow >> 1) & 3)) * 16);
                    ldm_x4(bhf[p], bd);
                    ldm_x4(blf[p], bd + 8192);
                }
#pragma unroll
                for (int mt = 0; mt < 2; ++mt)
#pragma unroll
                    for (int q = 0; q < 4; ++q)
                        mma_bf16(acc[mt][hb * 4 + q], ahf[mt],
                                 bhf[q >> 1][(q & 1) * 2], bhf[q >> 1][(q & 1) * 2 + 1]);
#pragma unroll
                for (int mt = 0; mt < 2; ++mt)
#pragma unroll
                    for (int q = 0; q < 4; ++q)
                        mma_bf16(acc[mt][hb * 4 + q], ahf[mt],
                                 blf[q >> 1][(q & 1) * 2], blf[q >> 1][(q & 1) * 2 + 1]);
#pragma unroll
                for (int mt = 0; mt < 2; ++mt)
#pragma unroll
                    for (int q = 0; q < 4; ++q)
                        mma_bf16(acc[mt][hb * 4 + q], alf[mt],
                                 bhf[q >> 1][(q & 1) * 2], bhf[q >> 1][(q & 1) * 2 + 1]);
            }
        }
        __syncthreads();
    }

    // ---- epilogue
    float* Cf2 = Cf;
    int ncol0 = n0;
    if (SPLITC) {
        const int g = n0 / H_;
        Cf2 = Cf + (size_t)g * B_ * H_;
        ncol0 = n0 - g * H_;
    }
    const int gid = lane >> 2;
    const int cp2 = (lane & 3) * 2;
#pragma unroll
    for (int mt = 0; mt < 2; ++mt) {
        const int r0 = m0 + wm + mt * 16 + gid;
#pragma unroll
        for (int nt = 0; nt < 8; ++nt) {
            const int cloc = wn + nt * 8 + cp2;
            if (SPLITC || n0 + cloc < N) {
                const int col = ncol0 + cloc;
                float x0 = acc[mt][nt][0], x1 = acc[mt][nt][1];
                float x2 = acc[mt][nt][2], x3 = acc[mt][nt][3];
                if (EPI >= 1) {
                    const float bb0 = bias[col], bb1 = bias[col + 1];
                    x0 += bb0; x1 += bb1; x2 += bb0; x3 += bb1;
                }
                if (EPI == 2) {
                    x0 = fmaxf(x0, 0.f); x1 = fmaxf(x1, 0.f);
                    x2 = fmaxf(x2, 0.f); x3 = fmaxf(x3, 0.f);
                    __nv_bfloat16 h0 = __float2bfloat16(x0), h1 = __float2bfloat16(x1);
                    __nv_bfloat16 h2 = __float2bfloat16(x2), h3 = __float2bfloat16(x3);
                    __nv_bfloat16 l0 = __float2bfloat16(x0 - __bfloat162float(h0));
                    __nv_bfloat16 l1 = __float2bfloat16(x1 - __bfloat162float(h1));
                    __nv_bfloat16 l2 = __float2bfloat16(x2 - __bfloat162float(h2));
                    __nv_bfloat16 l3 = __float2bfloat16(x3 - __bfloat162float(h3));
                    *(__nv_bfloat162*)(Chi + (size_t)r0 * ldc + col)       = __nv_bfloat162(h0, h1);
                    *(__nv_bfloat162*)(Chi + (size_t)(r0 + 8) * ldc + col) = __nv_bfloat162(h2, h3);
                    *(__nv_bfloat162*)(Clo + (size_t)r0 * ldc + col)       = __nv_bfloat162(l0, l1);
                    *(__nv_bfloat162*)(Clo + (size_t)(r0 + 8) * ldc + col) = __nv_bfloat162(l2, l3);
                } else {
                    *(float2*)(Cf2 + (size_t)r0 * ldc + col)       = make_float2(x0, x1);
                    *(float2*)(Cf2 + (size_t)(r0 + 8) * ldc + col) = make_float2(x2, x3);
                }
            }
        }
    }
}

// ---------------- fp32 -> bf16 hi/lo split (vec4) ----------------
__global__ void cvt_kernel(const float4* __restrict__ src,
                           __nv_bfloat16* __restrict__ hi,
                           __nv_bfloat16* __restrict__ lo, int n4)
{
    int i = blockIdx.x * blockDim.x + threadIdx.x;
    if (i < n4) {
        float4 x = src[i];
        __nv_bfloat16 h[4], l[4];
        const float* xs = (const float*)&x;
#pragma unroll
        for (int q = 0; q < 4; ++q) {
            h[q] = __float2bfloat16(xs[q]);
            l[q] = __float2bfloat16(xs[q] - __bfloat162float(h[q]));
        }
        *(uint2*)(hi + 4 * (size_t)i) = *(uint2*)h;
        *(uint2*)(lo + 4 * (size_t)i) = *(uint2*)l;
    }
}

// combined convert for the 4 output-MLP weight mats (packed dst)
__global__ void cvt4_kernel(const float* __restrict__ s0, const float* __restrict__ s1,
                            const float* __restrict__ s2, const float* __restrict__ s3,
                            __nv_bfloat16* __restrict__ hi, __nv_bfloat16* __restrict__ lo)
{
    const int n0 = S_ * S_, n1 = 2 * S_ * S_;
    const int n2 = 2 * S_ * S_ + Q_ * S_, n3 = 2 * S_ * S_ + 2 * Q_ * S_;
    int i = blockIdx.x * blockDim.x + threadIdx.x;
    if (i >= n3) return;
    float x;
    if      (i < n0) x = s0[i];
    else if (i < n1) x = s1[i - n0];
    else if (i < n2) x = s2[i - n1];
    else             x = s3[i - n2];
    __nv_bfloat16 h = __float2bfloat16(x);
    hi[i] = h;
    lo[i] = __float2bfloat16(x - __bfloat162float(h));
}

// ---------------- fused gate (vectorized x4, fast math) ----------------
__global__ void gate_kernel(const float* __restrict__ prev_y,
                            const float* __restrict__ prev_hidden,
                            const float* __restrict__ coarse,
                            const float* __restrict__ W_Ic,
                            const float* __restrict__ W_If,
                            const float* __restrict__ bias_u,
                            const float* __restrict__ bias_r,
                            const float* __restrict__ bias_e,
                            const float* __restrict__ Rbuf,
                            float* __restrict__ hidden_out,
                            __nv_bfloat16* __restrict__ hid_hi,
                            __nv_bfloat16* __restrict__ hid_lo)
{
    const int HV = H_ / 4;
    int v = blockIdx.x * blockDim.x + threadIdx.x;
    if (v >= B_ * HV) return;
    int b = v / HV;
    int j = (v - b * HV) * 4;
    size_t idx = (size_t)b * H_ + j;
    const size_t NBH = (size_t)B_ * H_;

    float py0 = prev_y[2 * b], py1 = prev_y[2 * b + 1];
    float4 Ru4 = *(const float4*)(Rbuf + idx);
    float4 Rr4 = *(const float4*)(Rbuf + NBH + idx);
    float4 Re4 = *(const float4*)(Rbuf + 2 * NBH + idx);
    float4 ph4 = *(const float4*)(prev_hidden + idx);

    float h[4];
    const float* Ru = (const float*)&Ru4;
    const float* Rr = (const float*)&Rr4;
    const float* Re = (const float*)&Re4;
    const float* ph = (const float*)&ph4;

    if (j < S_) {
#pragma unroll
        for (int q = 0; q < 4; ++q) {
            int jj = j + q;
            float Iu = py0 * W_Ic[jj * 2] + py1 * W_Ic[jj * 2 + 1];
            float Ir = py0 * W_Ic[(S_ + jj) * 2] + py1 * W_Ic[(S_ + jj) * 2 + 1];
            float Ie = py0 * W_Ic[(2 * S_ + jj) * 2] + py1 * W_Ic[(2 * S_ + jj) * 2 + 1];
            float u = fsigm(Ru[q] + Iu + bias_u[jj]);
            float r = fsigm(Rr[q] + Ir + bias_r[jj]);
            float e = ftanh(r * Re[q] + Ie + bias_e[jj]);
            h[q] = u * ph[q] + (1.f - u) * e;
        }
    } else {
        float cc = coarse[b];
#pragma unroll
        for (int q = 0; q < 4; ++q) {
            int jj = j + q;
            int jf = jj - S_;
            float Iu = py0 * W_If[jf * 3] + py1 * W_If[jf * 3 + 1] + cc * W_If[jf * 3 + 2];
            float Ir = py0 * W_If[(S_ + jf) * 3] + py1 * W_If[(S_ + jf) * 3 + 1] + cc * W_If[(S_ + jf) * 3 + 2];
            float Ie = py0 * W_If[(2 * S_ + jf) * 3] + py1 * W_If[(2 * S_ + jf) * 3 + 1] + cc * W_If[(2 * S_ + jf) * 3 + 2];
            float u = fsigm(Ru[q] + Iu + bias_u[jj]);
            float r = fsigm(Rr[q] + Ir + bias_r[jj]);
            float e = ftanh(r * Re[q] + Ie + bias_e[jj]);
            h[q] = u * ph[q] + (1.f - u) * e;
        }
    }

    *(float4*)(hidden_out + idx) = make_float4(h[0], h[1], h[2], h[3]);

    __nv_bfloat16 hh[4], hl[4];
#pragma unroll
    for (int q = 0; q < 4; ++q) {
        __nv_bfloat16 hi = __float2bfloat16(h[q]);
        hh[q] = hi;
        hl[q] = __float2bfloat16(h[q] - __bfloat162float(hi));
    }
    *(uint2*)(hid_hi + idx) = *(uint2*)hh;
    *(uint2*)(hid_lo + idx) = *(uint2*)hl;
}

// ---------------- launch ----------------
extern "C" void kernel_launch(void* const* d_in, const int* in_sizes, int n_in,
                              void* d_out, int out_size)
{
    const float* prev_y      = (const float*)d_in[0];
    const float* prev_hidden = (const float*)d_in[1];
    const float* coarse      = (const float*)d_in[2];
    const float* W_Ru        = (const float*)d_in[3];
    const float* W_Rr        = (const float*)d_in[4];
    const float* W_Re        = (const float*)d_in[5];
    const float* W_Ic        = (const float*)d_in[6];
    const float* W_If        = (const float*)d_in[7];
    const float* W_O1        = (const float*)d_in[8];
    const float* b_O1        = (const float*)d_in[9];
    const float* W_O2        = (const float*)d_in[10];
    const float* b_O2        = (const float*)d_in[11];
    const float* W_O3        = (const float*)d_in[12];
    const float* b_O3        = (const float*)d_in[13];
    const float* W_O4        = (const float*)d_in[14];
    const float* b_O4        = (const float*)d_in[15];
    const float* bias_u      = (const float*)d_in[16];
    const float* bias_r      = (const float*)d_in[17];
    const float* bias_e      = (const float*)d_in[18];

    float* out        = (float*)d_out;
    float* out_coarse = out;
    float* out_fine   = out + (size_t)B_ * Q_;
    float* hidden     = out + 2 * (size_t)B_ * Q_;

    float* Rbuf; __nv_bfloat16 *Ah, *Al, *Hh, *Hl, *Th, *Tl, *Wh, *Wl;
    cudaGetSymbolAddress((void**)&Rbuf, g_R);
    cudaGetSymbolAddress((void**)&Ah, g_Ah);
    cudaGetSymbolAddress((void**)&Al, g_Al);
    cudaGetSymbolAddress((void**)&Hh, g_Hh);
    cudaGetSymbolAddress((void**)&Hl, g_Hl);
    cudaGetSymbolAddress((void**)&Th, g_Th);
    cudaGetSymbolAddress((void**)&Tl, g_Tl);
    cudaGetSymbolAddress((void**)&Wh, g_Wh);
    cudaGetSymbolAddress((void**)&Wl, g_Wl);

    cudaFuncSetAttribute(gemm_mma<0, true>,  cudaFuncAttributeMaxDynamicSharedMemorySize, SMEM_TOTAL);
    cudaFuncSetAttribute(gemm_mma<1, false>, cudaFuncAttributeMaxDynamicSharedMemorySize, SMEM_TOTAL);
    cudaFuncSetAttribute(gemm_mma<2, false>, cudaFuncAttributeMaxDynamicSharedMemorySize, SMEM_TOTAL);

    const size_t NBS = (size_t)B_ * S_;
    dim3 blk(256);

    // launches 0-4: converts (profiler skips these with -s 5)
    cvt_kernel<<<(B_ * H_ / 4 + 255) / 256, 256>>>((const float4*)prev_hidden, Ah, Al, B_ * H_ / 4);
    cvt_kernel<<<(H_ * H_ / 4 + 255) / 256, 256>>>((const float4*)W_Ru, Wh + OFF_WR,             Wl + OFF_WR,             H_ * H_ / 4);
    cvt_kernel<<<(H_ * H_ / 4 + 255) / 256, 256>>>((const float4*)W_Rr, Wh + OFF_WR + H_ * H_,   Wl + OFF_WR + H_ * H_,   H_ * H_ / 4);
    cvt_kernel<<<(H_ * H_ / 4 + 255) / 256, 256>>>((const float4*)W_Re, Wh + OFF_WR + 2 * H_ * H_, Wl + OFF_WR + 2 * H_ * H_, H_ * H_ / 4);
    cvt4_kernel<<<((2 * S_ * S_ + 2 * Q_ * S_) + 255) / 256, 256>>>(W_O1, W_O3, W_O2, W_O4,
                                                                    Wh + OFF_WO1, Wl + OFF_WO1);

    // launch 5 (profiled): fused recurrent projections, N = 3*H = 2688
    dim3 g1(3 * H_ / 128, B_ / 128);  // (21, 64)
    gemm_mma<0, true><<<g1, blk, SMEM_TOTAL>>>(Ah, Al, H_, Wh + OFF_WR, Wl + OFF_WR,
                                               3 * H_, H_, nullptr, Rbuf, nullptr, nullptr, H_);

    // fused gates -> hidden (fp32 to d_out) + bf16 hi/lo pair
    gate_kernel<<<(B_ * (H_ / 4) + 255) / 256, 256>>>(prev_y, prev_hidden, coarse, W_Ic, W_If,
                                                      bias_u, bias_r, bias_e, Rbuf, hidden, Hh, Hl);

    // relu(h_half @ W^T + b) -> bf16 pair scratch
    dim3 g2((S_ + 127) / 128, B_ / 128);  // (4, 64)
    gemm_mma<2, false><<<g2, blk, SMEM_TOTAL>>>(Hh, Hl, H_, Wh + OFF_WO1, Wl + OFF_WO1, S_, S_,
                                                b_O1, nullptr, Th, Tl, S_);
    gemm_mma<2, false><<<g2, blk, SMEM_TOTAL>>>(Hh + S_, Hl + S_, H_, Wh + OFF_WO3, Wl + OFF_WO3, S_, S_,
                                                b_O3, nullptr, Th + NBS, Tl + NBS, S_);

    // logits -> d_out
    dim3 g3(Q_ / 128, B_ / 128);  // (2, 64)
    gemm_mma<1, false><<<g3, blk, SMEM_TOTAL>>>(Th, Tl, S_, Wh + OFF_WO2, Wl + OFF_WO2, Q_, S_,
                                                b_O2, out_coarse, nullptr, nullptr, Q_);
    gemm_mma<1, false><<<g3, blk, SMEM_TOTAL>>>(Th + NBS, Tl + NBS, S_, Wh + OFF_WO4, Wl + OFF_WO4, Q_, S_,
                                                b_O4, out_fine, nullptr, nullptr, Q_);
}

// round 6
// speedup vs baseline: 4.0765x; 1.3697x over previous
#include <cuda_runtime.h>
#include <cuda_fp16.h>
#include <math.h>
#include <stdint.h>

#define B_ 8192
#define H_ 896
#define S_ 448
#define Q_ 256

// ---------------- scratch (allocation-free __device__ globals) ----------------
__device__ float g_R[3ull * B_ * H_];                    // R_u | R_r | R_e
__device__ __half g_Ah[(size_t)B_ * H_];
__device__ __half g_Al[(size_t)B_ * H_];
__device__ __half g_Hh[(size_t)B_ * H_];
__device__ __half g_Hl[(size_t)B_ * H_];
__device__ __half g_Th[2ull * B_ * S_];
__device__ __half g_Tl[2ull * B_ * S_];
#define WSZ (3 * H_ * H_ + 2 * S_ * S_ + 2 * Q_ * S_)
__device__ __half g_Wh[WSZ];

#define OFF_WR  0
#define OFF_WO1 (3 * H_ * H_)
#define OFF_WO3 (3 * H_ * H_ + S_ * S_)
#define OFF_WO2 (3 * H_ * H_ + 2 * S_ * S_)
#define OFF_WO4 (3 * H_ * H_ + 2 * S_ * S_ + Q_ * S_)

// ---------------- PTX helpers (base sm_80+ features only) ----------------
__device__ __forceinline__ uint32_t s2u(const void* p) {
    return (uint32_t)__cvta_generic_to_shared(p);
}
__device__ __forceinline__ void cp_async16(uint32_t dst, const void* src, uint32_t bytes) {
    asm volatile("cp.async.cg.shared.global [%0], [%1], 16, %2;"
                 :: "r"(dst), "l"(src), "r"(bytes) : "memory");
}
__device__ __forceinline__ void cp_commit() {
    asm volatile("cp.async.commit_group;" ::: "memory");
}
template<int NN>
__device__ __forceinline__ void cp_wait() {
    asm volatile("cp.async.wait_group %0;" :: "n"(NN) : "memory");
}
__device__ __forceinline__ void ldm_x4(uint32_t* r, uint32_t addr) {
    asm volatile("ldmatrix.sync.aligned.m8n8.x4.shared.b16 {%0,%1,%2,%3}, [%4];"
                 : "=r"(r[0]), "=r"(r[1]), "=r"(r[2]), "=r"(r[3]) : "r"(addr));
}
__device__ __forceinline__ void mma_fp16(float* d, const uint32_t* a, uint32_t b0, uint32_t b1) {
    asm volatile("mma.sync.aligned.m16n8k16.row.col.f32.f16.f16.f32 "
                 "{%0,%1,%2,%3}, {%4,%5,%6,%7}, {%8,%9}, {%0,%1,%2,%3};"
                 : "+f"(d[0]), "+f"(d[1]), "+f"(d[2]), "+f"(d[3])
                 : "r"(a[0]), "r"(a[1]), "r"(a[2]), "r"(a[3]), "r"(b0), "r"(b1));
}
__device__ __forceinline__ float ftanh(float x) {
    float y; asm("tanh.approx.f32 %0, %1;" : "=f"(y) : "f"(x)); return y;
}
__device__ __forceinline__ float fsigm(float x) {
    return 1.0f / (1.0f + __expf(-x));
}

// ---------------- GEMM: C[M,N] = (Ah+Al)[M,K] @ Wh[N,K]^T  (fp16, 2 terms) ------
// 128x128x32 tiles, 4-stage cp.async pipeline, one barrier per chunk.
// stage layout: Ah(8K) | Al(8K) | Wh(8K) = 24KB
// EPI: 0 = fp32, 1 = +bias fp32, 2 = relu(+bias) -> fp16 hi/lo pair
#define STAGE_BYTES 24576
#define NSTAGE 4
#define SMEM_TOTAL (NSTAGE * STAGE_BYTES)

template<int EPI, bool SPLITC>
__global__ __launch_bounds__(256, 2)
void gemm_mma(const __half* __restrict__ Ah, const __half* __restrict__ Al, int lda,
              const __half* __restrict__ Wh,
              int N, int K, const float* __restrict__ bias,
              float* __restrict__ Cf, __half* __restrict__ Chi,
              __half* __restrict__ Clo, int ldc)
{
    extern __shared__ char smem[];
    const int t  = threadIdx.x;
    const int m0 = blockIdx.y * 128;
    const int n0 = blockIdx.x * 128;
    const int tile_n = SPLITC ? 128 : min(128, N - n0);
    const uint32_t sb0 = s2u(smem);
    const int lane = t & 31;
    const int wid  = t >> 5;
    const int wm = (wid & 3) * 32;
    const int wn = (wid >> 2) * 64;

    float acc[2][8][4];
#pragma unroll
    for (int a = 0; a < 2; a++)
#pragma unroll
        for (int b = 0; b < 8; b++)
#pragma unroll
            for (int d = 0; d < 4; d++) acc[a][b][d] = 0.f;

    const int nch = K / 32;

    auto load_stage = [&](int c, int st) {
        const int k0 = c * 32;
        const uint32_t sb = sb0 + st * STAGE_BYTES;
#pragma unroll
        for (int i = 0; i < 6; ++i) {
            const int tile   = i >> 1;              // 0=Ah, 1=Al, 2=Wh
            const int within = t + (i & 1) * 256;   // 0..511
            const int row    = within >> 2;
            const int ch     = within & 3;
            const uint32_t dst = sb + tile * 8192 + row * 64 +
                                 ((ch ^ ((row >> 1) & 3)) * 16);
            if (tile < 2) {
                const __half* base = (tile == 0) ? Ah : Al;
                cp_async16(dst, base + (size_t)(m0 + row) * lda + k0 + ch * 8, 16);
            } else {
                const int r = (row < tile_n) ? row : (tile_n - 1);
                cp_async16(dst, Wh + (size_t)(n0 + r) * K + k0 + ch * 8,
                           (row < tile_n) ? 16u : 0u);
            }
        }
        cp_commit();
    };

    load_stage(0, 0);
    if (nch > 1) load_stage(1, 1);

    const int arow = (lane & 7) + ((lane >> 3) & 1) * 8;
    const int asel = (lane >> 4) & 1;
    const int brow = (lane & 7) + ((lane >> 4) & 1) * 8;
    const int bsel = (lane >> 3) & 1;

    for (int c = 0; c < nch; ++c) {
        if (c + 2 < nch) { load_stage(c + 2, (c + 2) & 3); cp_wait<2>(); }
        else if (c + 1 < nch) { cp_wait<1>(); }
        else { cp_wait<0>(); }
        __syncthreads();
        const uint32_t sb = sb0 + (c & 3) * STAGE_BYTES;
#pragma unroll
        for (int ks = 0; ks < 2; ++ks) {
            uint32_t ahf[2][4], alf[2][4];
            const int ach = ks * 2 + asel;
#pragma unroll
            for (int mt = 0; mt < 2; ++mt) {
                const int row = wm + mt * 16 + arow;
                const uint32_t ad = sb + row * 64 + ((ach ^ ((row >> 1) & 3)) * 16);
                ldm_x4(ahf[mt], ad);
                ldm_x4(alf[mt], ad + 8192);
            }
            const int bch = ks * 2 + bsel;
#pragma unroll
            for (int hb = 0; hb < 2; ++hb) {
                uint32_t bhf[2][4];
#pragma unroll
                for (int p = 0; p < 2; ++p) {
                    const int nrow = wn + hb * 32 + p * 16 + brow;
                    const uint32_t bd = sb + 16384 + nrow * 64 +
                                        ((bch ^ ((nrow >> 1) & 3)) * 16);
                    ldm_x4(bhf[p], bd);
                }
#pragma unroll
                for (int mt = 0; mt < 2; ++mt)
#pragma unroll
                    for (int q = 0; q < 4; ++q)
                        mma_fp16(acc[mt][hb * 4 + q], ahf[mt],
                                 bhf[q >> 1][(q & 1) * 2], bhf[q >> 1][(q & 1) * 2 + 1]);
#pragma unroll
                for (int mt = 0; mt < 2; ++mt)
#pragma unroll
                    for (int q = 0; q < 4; ++q)
                        mma_fp16(acc[mt][hb * 4 + q], alf[mt],
                                 bhf[q >> 1][(q & 1) * 2], bhf[q >> 1][(q & 1) * 2 + 1]);
            }
        }
    }

    // ---- epilogue
    float* Cf2 = Cf;
    int ncol0 = n0;
    if (SPLITC) {
        const int g = n0 / H_;
        Cf2 = Cf + (size_t)g * B_ * H_;
        ncol0 = n0 - g * H_;
    }
    const int gid = lane >> 2;
    const int cp2 = (lane & 3) * 2;
#pragma unroll
    for (int mt = 0; mt < 2; ++mt) {
        const int r0 = m0 + wm + mt * 16 + gid;
#pragma unroll
        for (int nt = 0; nt < 8; ++nt) {
            const int cloc = wn + nt * 8 + cp2;
            if (SPLITC || n0 + cloc < N) {
                const int col = ncol0 + cloc;
                float x0 = acc[mt][nt][0], x1 = acc[mt][nt][1];
                float x2 = acc[mt][nt][2], x3 = acc[mt][nt][3];
                if (EPI >= 1) {
                    const float bb0 = bias[col], bb1 = bias[col + 1];
                    x0 += bb0; x1 += bb1; x2 += bb0; x3 += bb1;
                }
                if (EPI == 2) {
                    x0 = fmaxf(x0, 0.f); x1 = fmaxf(x1, 0.f);
                    x2 = fmaxf(x2, 0.f); x3 = fmaxf(x3, 0.f);
                    __half h0 = __float2half(x0), h1 = __float2half(x1);
                    __half h2 = __float2half(x2), h3 = __float2half(x3);
                    __half l0 = __float2half(x0 - __half2float(h0));
                    __half l1 = __float2half(x1 - __half2float(h1));
                    __half l2 = __float2half(x2 - __half2float(h2));
                    __half l3 = __float2half(x3 - __half2float(h3));
                    *(__half2*)(Chi + (size_t)r0 * ldc + col)       = __halves2half2(h0, h1);
                    *(__half2*)(Chi + (size_t)(r0 + 8) * ldc + col) = __halves2half2(h2, h3);
                    *(__half2*)(Clo + (size_t)r0 * ldc + col)       = __halves2half2(l0, l1);
                    *(__half2*)(Clo + (size_t)(r0 + 8) * ldc + col) = __halves2half2(l2, l3);
                } else {
                    *(float2*)(Cf2 + (size_t)r0 * ldc + col)       = make_float2(x0, x1);
                    *(float2*)(Cf2 + (size_t)(r0 + 8) * ldc + col) = make_float2(x2, x3);
                }
            }
        }
    }
}

// ---------------- fp32 -> fp16 hi/lo split (vec4) ----------------
__global__ void cvtA_kernel(const float4* __restrict__ src,
                            __half* __restrict__ hi,
                            __half* __restrict__ lo, int n4)
{
    int i = blockIdx.x * blockDim.x + threadIdx.x;
    if (i < n4) {
        float4 x = src[i];
        __half h[4], l[4];
        const float* xs = (const float*)&x;
#pragma unroll
        for (int q = 0; q < 4; ++q) {
            h[q] = __float2half(xs[q]);
            l[q] = __float2half(xs[q] - __half2float(h[q]));
        }
        *(uint2*)(hi + 4 * (size_t)i) = *(uint2*)h;
        *(uint2*)(lo + 4 * (size_t)i) = *(uint2*)l;
    }
}

// fp32 -> fp16 single (vec4)
__global__ void cvtW_kernel(const float4* __restrict__ src,
                            __half* __restrict__ dst, int n4)
{
    int i = blockIdx.x * blockDim.x + threadIdx.x;
    if (i < n4) {
        float4 x = src[i];
        __half h[4];
        h[0] = __float2half(x.x); h[1] = __float2half(x.y);
        h[2] = __float2half(x.z); h[3] = __float2half(x.w);
        *(uint2*)(dst + 4 * (size_t)i) = *(uint2*)h;
    }
}

// combined single-precision convert for the 4 output-MLP weight mats
__global__ void cvtW4_kernel(const float* __restrict__ s0, const float* __restrict__ s1,
                             const float* __restrict__ s2, const float* __restrict__ s3,
                             __half* __restrict__ dst)
{
    const int n0 = S_ * S_, n1 = 2 * S_ * S_;
    const int n2 = 2 * S_ * S_ + Q_ * S_, n3 = 2 * S_ * S_ + 2 * Q_ * S_;
    int i = blockIdx.x * blockDim.x + threadIdx.x;
    if (i >= n3) return;
    float x;
    if      (i < n0) x = s0[i];
    else if (i < n1) x = s1[i - n0];
    else if (i < n2) x = s2[i - n1];
    else             x = s3[i - n2];
    dst[i] = __float2half(x);
}

// ---------------- fused gate (vectorized x4, fast math) ----------------
__global__ void gate_kernel(const float* __restrict__ prev_y,
                            const float* __restrict__ prev_hidden,
                            const float* __restrict__ coarse,
                            const float* __restrict__ W_Ic,
                            const float* __restrict__ W_If,
                            const float* __restrict__ bias_u,
                            const float* __restrict__ bias_r,
                            const float* __restrict__ bias_e,
                            const float* __restrict__ Rbuf,
                            float* __restrict__ hidden_out,
                            __half* __restrict__ hid_hi,
                            __half* __restrict__ hid_lo)
{
    const int HV = H_ / 4;
    int v = blockIdx.x * blockDim.x + threadIdx.x;
    if (v >= B_ * HV) return;
    int b = v / HV;
    int j = (v - b * HV) * 4;
    size_t idx = (size_t)b * H_ + j;
    const size_t NBH = (size_t)B_ * H_;

    float py0 = prev_y[2 * b], py1 = prev_y[2 * b + 1];
    float4 Ru4 = *(const float4*)(Rbuf + idx);
    float4 Rr4 = *(const float4*)(Rbuf + NBH + idx);
    float4 Re4 = *(const float4*)(Rbuf + 2 * NBH + idx);
    float4 ph4 = *(const float4*)(prev_hidden + idx);

    float h[4];
    const float* Ru = (const float*)&Ru4;
    const float* Rr = (const float*)&Rr4;
    const float* Re = (const float*)&Re4;
    const float* ph = (const float*)&ph4;

    if (j < S_) {
#pragma unroll
        for (int q = 0; q < 4; ++q) {
            int jj = j + q;
            float Iu = py0 * W_Ic[jj * 2] + py1 * W_Ic[jj * 2 + 1];
            float Ir = py0 * W_Ic[(S_ + jj) * 2] + py1 * W_Ic[(S_ + jj) * 2 + 1];
            float Ie = py0 * W_Ic[(2 * S_ + jj) * 2] + py1 * W_Ic[(2 * S_ + jj) * 2 + 1];
            float u = fsigm(Ru[q] + Iu + bias_u[jj]);
            float r = fsigm(Rr[q] + Ir + bias_r[jj]);
            float e = ftanh(r * Re[q] + Ie + bias_e[jj]);
            h[q] = u * ph[q] + (1.f - u) * e;
        }
    } else {
        float cc = coarse[b];
#pragma unroll
        for (int q = 0; q < 4; ++q) {
            int jj = j + q;
            int jf = jj - S_;
            float Iu = py0 * W_If[jf * 3] + py1 * W_If[jf * 3 + 1] + cc * W_If[jf * 3 + 2];
            float Ir = py0 * W_If[(S_ + jf) * 3] + py1 * W_If[(S_ + jf) * 3 + 1] + cc * W_If[(S_ + jf) * 3 + 2];
            float Ie = py0 * W_If[(2 * S_ + jf) * 3] + py1 * W_If[(2 * S_ + jf) * 3 + 1] + cc * W_If[(2 * S_ + jf) * 3 + 2];
            float u = fsigm(Ru[q] + Iu + bias_u[jj]);
            float r = fsigm(Rr[q] + Ir + bias_r[jj]);
            float e = ftanh(r * Re[q] + Ie + bias_e[jj]);
            h[q] = u * ph[q] + (1.f - u) * e;
        }
    }

    *(float4*)(hidden_out + idx) = make_float4(h[0], h[1], h[2], h[3]);

    __half hh[4], hl[4];
#pragma unroll
    for (int q = 0; q < 4; ++q) {
        __half hi = __float2half(h[q]);
        hh[q] = hi;
        hl[q] = __float2half(h[q] - __half2float(hi));
    }
    *(uint2*)(hid_hi + idx) = *(uint2*)hh;
    *(uint2*)(hid_lo + idx) = *(uint2*)hl;
}

// ---------------- launch ----------------
extern "C" void kernel_launch(void* const* d_in, const int* in_sizes, int n_in,
                              void* d_out, int out_size)
{
    const float* prev_y      = (const float*)d_in[0];
    const float* prev_hidden = (const float*)d_in[1];
    const float* coarse      = (const float*)d_in[2];
    const float* W_Ru        = (const float*)d_in[3];
    const float* W_Rr        = (const float*)d_in[4];
    const float* W_Re        = (const float*)d_in[5];
    const float* W_Ic        = (const float*)d_in[6];
    const float* W_If        = (const float*)d_in[7];
    const float* W_O1        = (const float*)d_in[8];
    const float* b_O1        = (const float*)d_in[9];
    const float* W_O2        = (const float*)d_in[10];
    const float* b_O2        = (const float*)d_in[11];
    const float* W_O3        = (const float*)d_in[12];
    const float* b_O3        = (const float*)d_in[13];
    const float* W_O4        = (const float*)d_in[14];
    const float* b_O4        = (const float*)d_in[15];
    const float* bias_u      = (const float*)d_in[16];
    const float* bias_r      = (const float*)d_in[17];
    const float* bias_e      = (const float*)d_in[18];

    float* out        = (float*)d_out;
    float* out_coarse = out;
    float* out_fine   = out + (size_t)B_ * Q_;
    float* hidden     = out + 2 * (size_t)B_ * Q_;

    float* Rbuf; __half *Ah, *Al, *Hh, *Hl, *Th, *Tl, *Wh;
    cudaGetSymbolAddress((void**)&Rbuf, g_R);
    cudaGetSymbolAddress((void**)&Ah, g_Ah);
    cudaGetSymbolAddress((void**)&Al, g_Al);
    cudaGetSymbolAddress((void**)&Hh, g_Hh);
    cudaGetSymbolAddress((void**)&Hl, g_Hl);
    cudaGetSymbolAddress((void**)&Th, g_Th);
    cudaGetSymbolAddress((void**)&Tl, g_Tl);
    cudaGetSymbolAddress((void**)&Wh, g_Wh);

    cudaFuncSetAttribute(gemm_mma<0, true>,  cudaFuncAttributeMaxDynamicSharedMemorySize, SMEM_TOTAL);
    cudaFuncSetAttribute(gemm_mma<1, false>, cudaFuncAttributeMaxDynamicSharedMemorySize, SMEM_TOTAL);
    cudaFuncSetAttribute(gemm_mma<2, false>, cudaFuncAttributeMaxDynamicSharedMemorySize, SMEM_TOTAL);

    const size_t NBS = (size_t)B_ * S_;
    dim3 blk(256);

    // converts
    cvtA_kernel<<<(B_ * H_ / 4 + 255) / 256, 256>>>((const float4*)prev_hidden, Ah, Al, B_ * H_ / 4);
    cvtW_kernel<<<(H_ * H_ / 4 + 255) / 256, 256>>>((const float4*)W_Ru, Wh + OFF_WR,              H_ * H_ / 4);
    cvtW_kernel<<<(H_ * H_ / 4 + 255) / 256, 256>>>((const float4*)W_Rr, Wh + OFF_WR + H_ * H_,    H_ * H_ / 4);
    cvtW_kernel<<<(H_ * H_ / 4 + 255) / 256, 256>>>((const float4*)W_Re, Wh + OFF_WR + 2 * H_ * H_, H_ * H_ / 4);
    cvtW4_kernel<<<((2 * S_ * S_ + 2 * Q_ * S_) + 255) / 256, 256>>>(W_O1, W_O3, W_O2, W_O4, Wh + OFF_WO1);

    // fused recurrent projections, N = 3*H = 2688
    dim3 g1(3 * H_ / 128, B_ / 128);  // (21, 64)
    gemm_mma<0, true><<<g1, blk, SMEM_TOTAL>>>(Ah, Al, H_, Wh + OFF_WR,
                                               3 * H_, H_, nullptr, Rbuf, nullptr, nullptr, H_);

    // fused gates -> hidden (fp32 to d_out) + fp16 hi/lo pair
    gate_kernel<<<(B_ * (H_ / 4) + 255) / 256, 256>>>(prev_y, prev_hidden, coarse, W_Ic, W_If,
                                                      bias_u, bias_r, bias_e, Rbuf, hidden, Hh, Hl);

    // relu(h_half @ W^T + b) -> fp16 pair scratch
    dim3 g2((S_ + 127) / 128, B_ / 128);  // (4, 64)
    gemm_mma<2, false><<<g2, blk, SMEM_TOTAL>>>(Hh, Hl, H_, Wh + OFF_WO1, S_, S_,
                                                b_O1, nullptr, Th, Tl, S_);
    gemm_mma<2, false><<<g2, blk, SMEM_TOTAL>>>(Hh + S_, Hl + S_, H_, Wh + OFF_WO3, S_, S_,
                                                b_O3, nullptr, Th + NBS, Tl + NBS, S_);

    // logits -> d_out
    dim3 g3(Q_ / 128, B_ / 128);  // (2, 64)
    gemm_mma<1, false><<<g3, blk, SMEM_TOTAL>>>(Th, Tl, S_, Wh + OFF_WO2, Q_, S_,
                                                b_O2, out_coarse, nullptr, nullptr, Q_);
    gemm_mma<1, false><<<g3, blk, SMEM_TOTAL>>>(Th + NBS, Tl + NBS, S_, Wh + OFF_WO4, Q_, S_,
                                                b_O4, out_fine, nullptr, nullptr, Q_);
}

// round 8
// speedup vs baseline: 5.4146x; 1.3283x over previous
#include <cuda_runtime.h>
#include <cuda_fp16.h>
#include <math.h>
#include <stdint.h>

#define B_ 8192
#define H_ 896
#define S_ 448
#define Q_ 256

// ---------------- scratch (allocation-free __device__ globals) ----------------
__device__ float g_R[3ull * B_ * H_];                    // R_u | R_r | R_e
__device__ __half g_Ah[(size_t)B_ * H_];
__device__ __half g_Hh[(size_t)B_ * H_];
__device__ __half g_Hl[(size_t)B_ * H_];
__device__ __half g_Th[2ull * B_ * S_];
__device__ __half g_Tl[2ull * B_ * S_];
#define WSZ (3 * H_ * H_ + 2 * S_ * S_ + 2 * Q_ * S_)
__device__ __half g_Wh[WSZ];

#define OFF_WR  0
#define OFF_WO1 (3 * H_ * H_)
#define OFF_WO2 (3 * H_ * H_ + 2 * S_ * S_)

// ---------------- PTX helpers (base sm_80+ features only) ----------------
__device__ __forceinline__ uint32_t s2u(const void* p) {
    return (uint32_t)__cvta_generic_to_shared(p);
}
__device__ __forceinline__ void cp_async16(uint32_t dst, const void* src, uint32_t bytes) {
    asm volatile("cp.async.cg.shared.global [%0], [%1], 16, %2;"
                 :: "r"(dst), "l"(src), "r"(bytes) : "memory");
}
__device__ __forceinline__ void cp_commit() {
    asm volatile("cp.async.commit_group;" ::: "memory");
}
template<int NN>
__device__ __forceinline__ void cp_wait() {
    asm volatile("cp.async.wait_group %0;" :: "n"(NN) : "memory");
}
__device__ __forceinline__ void ldm_x4(uint32_t* r, uint32_t addr) {
    asm volatile("ldmatrix.sync.aligned.m8n8.x4.shared.b16 {%0,%1,%2,%3}, [%4];"
                 : "=r"(r[0]), "=r"(r[1]), "=r"(r[2]), "=r"(r[3]) : "r"(addr));
}
__device__ __forceinline__ void mma_fp16(float* d, const uint32_t* a, uint32_t b0, uint32_t b1) {
    asm volatile("mma.sync.aligned.m16n8k16.row.col.f32.f16.f16.f32 "
                 "{%0,%1,%2,%3}, {%4,%5,%6,%7}, {%8,%9}, {%0,%1,%2,%3};"
                 : "+f"(d[0]), "+f"(d[1]), "+f"(d[2]), "+f"(d[3])
                 : "r"(a[0]), "r"(a[1]), "r"(a[2]), "r"(a[3]), "r"(b0), "r"(b1));
}
__device__ __forceinline__ float ftanh(float x) {
    float y; asm("tanh.approx.f32 %0, %1;" : "=f"(y) : "f"(x)); return y;
}
__device__ __forceinline__ float fsigm(float x) {
    return 1.0f / (1.0f + __expf(-x));
}

// ---------------- GEMM: C[M,N] = (Ah [+ Al])[M,K] @ Wh[N,K]^T -----------------
// 128x128x32 tiles, cp.async pipeline with LOOK = NST-2 (loads are issued
// BEFORE the per-chunk barrier, so the write target (c+LOOK)%NST must differ
// from the stage laggard warps may still read, (c-1)%NST -> LOOK <= NST-2).
// TERMS=1: pure fp16 A. TERMS=2: A split hi/lo (2 MMA terms).
// stage: Ah(8K) [| Al(8K)] | Wh(8K)
// EPI: 0 = fp32, 1 = +bias fp32, 2 = relu(+bias) -> fp16 hi/lo pair
// grid.z batches two independent GEMMs (zA/zW/zC element strides, bias0/bias1).
template<int EPI, bool SPLITC, int TERMS>
__global__ __launch_bounds__(256, 2)
void gemm_mma(const __half* __restrict__ Ah, const __half* __restrict__ Al, int lda,
              const __half* __restrict__ Wh,
              int N, int K, const float* __restrict__ bias0, const float* __restrict__ bias1,
              float* __restrict__ Cf, __half* __restrict__ Chi,
              __half* __restrict__ Clo, int ldc,
              int zA, int zW, int zC)
{
    constexpr int SBYTES = (TERMS == 2) ? 24576 : 16384;
    constexpr int NST    = (TERMS == 2) ? 4 : 5;
    constexpr int LOOK   = NST - 2;          // see header comment: NST-2 is the max safe lookahead
    constexpr int WOFS   = TERMS * 8192;

    extern __shared__ char smem[];
    const int z = blockIdx.z;
    Ah += (size_t)z * zA;
    if (TERMS == 2) Al += (size_t)z * zA;
    Wh += (size_t)z * zW;
    const float* bias = z ? bias1 : bias0;

    const int t  = threadIdx.x;
    const int m0 = blockIdx.y * 128;
    const int n0 = blockIdx.x * 128;
    const int tile_n = SPLITC ? 128 : min(128, N - n0);
    const uint32_t sb0 = s2u(smem);
    const int lane = t & 31;
    const int wid  = t >> 5;
    const int wm = (wid & 3) * 32;
    const int wn = (wid >> 2) * 64;

    float acc[2][8][4];
#pragma unroll
    for (int a = 0; a < 2; a++)
#pragma unroll
        for (int b = 0; b < 8; b++)
#pragma unroll
            for (int d = 0; d < 4; d++) acc[a][b][d] = 0.f;

    const int nch = K / 32;

    auto load_stage = [&](int c, int st) {
        const int k0 = c * 32;
        const uint32_t sb = sb0 + st * SBYTES;
#pragma unroll
        for (int i = 0; i < 2 * (TERMS + 1); ++i) {
            const int tile   = i >> 1;
            const int within = t + (i & 1) * 256;   // 0..511
            const int row    = within >> 2;
            const int ch     = within & 3;
            const uint32_t dst = sb + tile * 8192 + row * 64 +
                                 ((ch ^ ((row >> 1) & 3)) * 16);
            if (tile < TERMS) {
                const __half* base = (tile == 0) ? Ah : Al;
                cp_async16(dst, base + (size_t)(m0 + row) * lda + k0 + ch * 8, 16);
            } else {
                const int r = (row < tile_n) ? row : (tile_n - 1);
                cp_async16(dst, Wh + (size_t)(n0 + r) * K + k0 + ch * 8,
                           (row < tile_n) ? 16u : 0u);
            }
        }
        cp_commit();
    };

#pragma unroll
    for (int s = 0; s < LOOK; ++s)
        if (s < nch) load_stage(s, s);

    const int arow = (lane & 7) + ((lane >> 3) & 1) * 8;
    const int asel = (lane >> 4) & 1;
    const int brow = (lane & 7) + ((lane >> 4) & 1) * 8;
    const int bsel = (lane >> 3) & 1;

    for (int c = 0; c < nch; ++c) {
        if (c + LOOK < nch) { load_stage(c + LOOK, (c + LOOK) % NST); cp_wait<LOOK>(); }
        else {
            const int rem = nch - 1 - c;    // 0..LOOK-1
            if (rem >= 2)      cp_wait<2>();
            else if (rem == 1) cp_wait<1>();
            else               cp_wait<0>();
        }
        __syncthreads();
        const uint32_t sb = sb0 + (c % NST) * SBYTES;
#pragma unroll
        for (int ks = 0; ks < 2; ++ks) {
            uint32_t ahf[2][4], alf[2][4];
            const int ach = ks * 2 + asel;
#pragma unroll
            for (int mt = 0; mt < 2; ++mt) {
                const int row = wm + mt * 16 + arow;
                const uint32_t ad = sb + row * 64 + ((ach ^ ((row >> 1) & 3)) * 16);
                ldm_x4(ahf[mt], ad);
                if (TERMS == 2) ldm_x4(alf[mt], ad + 8192);
            }
            const int bch = ks * 2 + bsel;
#pragma unroll
            for (int hb = 0; hb < 2; ++hb) {
                uint32_t bhf[2][4];
#pragma unroll
                for (int p = 0; p < 2; ++p) {
                    const int nrow = wn + hb * 32 + p * 16 + brow;
                    const uint32_t bd = sb + WOFS + nrow * 64 +
                                        ((bch ^ ((nrow >> 1) & 3)) * 16);
                    ldm_x4(bhf[p], bd);
                }
#pragma unroll
                for (int mt = 0; mt < 2; ++mt)
#pragma unroll
                    for (int q = 0; q < 4; ++q)
                        mma_fp16(acc[mt][hb * 4 + q], ahf[mt],
                                 bhf[q >> 1][(q & 1) * 2], bhf[q >> 1][(q & 1) * 2 + 1]);
                if (TERMS == 2) {
#pragma unroll
                    for (int mt = 0; mt < 2; ++mt)
#pragma unroll
                        for (int q = 0; q < 4; ++q)
                            mma_fp16(acc[mt][hb * 4 + q], alf[mt],
                                     bhf[q >> 1][(q & 1) * 2], bhf[q >> 1][(q & 1) * 2 + 1]);
                }
            }
        }
    }

    // ---- epilogue
    float* Cf2 = Cf + (size_t)z * zC;
    __half* Chi2 = Chi + (size_t)z * zC;
    __half* Clo2 = Clo + (size_t)z * zC;
    int ncol0 = n0;
    if (SPLITC) {
        const int g = n0 / H_;
        Cf2 = Cf + (size_t)g * B_ * H_;
        ncol0 = n0 - g * H_;
    }
    const int gid = lane >> 2;
    const int cp2 = (lane & 3) * 2;
#pragma unroll
    for (int mt = 0; mt < 2; ++mt) {
        const int r0 = m0 + wm + mt * 16 + gid;
#pragma unroll
        for (int nt = 0; nt < 8; ++nt) {
            const int cloc = wn + nt * 8 + cp2;
            if (SPLITC || n0 + cloc < N) {
                const int col = ncol0 + cloc;
                float x0 = acc[mt][nt][0], x1 = acc[mt][nt][1];
                float x2 = acc[mt][nt][2], x3 = acc[mt][nt][3];
                if (EPI >= 1) {
                    const float bb0 = bias[col], bb1 = bias[col + 1];
                    x0 += bb0; x1 += bb1; x2 += bb0; x3 += bb1;
                }
                if (EPI == 2) {
                    x0 = fmaxf(x0, 0.f); x1 = fmaxf(x1, 0.f);
                    x2 = fmaxf(x2, 0.f); x3 = fmaxf(x3, 0.f);
                    __half h0 = __float2half(x0), h1 = __float2half(x1);
                    __half h2 = __float2half(x2), h3 = __float2half(x3);
                    __half l0 = __float2half(x0 - __half2float(h0));
                    __half l1 = __float2half(x1 - __half2float(h1));
                    __half l2 = __float2half(x2 - __half2float(h2));
                    __half l3 = __float2half(x3 - __half2float(h3));
                    *(__half2*)(Chi2 + (size_t)r0 * ldc + col)       = __halves2half2(h0, h1);
                    *(__half2*)(Chi2 + (size_t)(r0 + 8) * ldc + col) = __halves2half2(h2, h3);
                    *(__half2*)(Clo2 + (size_t)r0 * ldc + col)       = __halves2half2(l0, l1);
                    *(__half2*)(Clo2 + (size_t)(r0 + 8) * ldc + col) = __halves2half2(l2, l3);
                } else {
                    *(float2*)(Cf2 + (size_t)r0 * ldc + col)       = make_float2(x0, x1);
                    *(float2*)(Cf2 + (size_t)(r0 + 8) * ldc + col) = make_float2(x2, x3);
                }
            }
        }
    }
}

// ---------------- fp32 -> fp16 (vec4) ----------------
__global__ void cvtW_kernel(const float4* __restrict__ src,
                            __half* __restrict__ dst, int n4)
{
    int i = blockIdx.x * blockDim.x + threadIdx.x;
    if (i < n4) {
        float4 x = src[i];
        __half h[4];
        h[0] = __float2half(x.x); h[1] = __float2half(x.y);
        h[2] = __float2half(x.z); h[3] = __float2half(x.w);
        *(uint2*)(dst + 4 * (size_t)i) = *(uint2*)h;
    }
}

// merged convert: 3 recurrent weight mats -> packed fp16
__global__ void cvtWR3_kernel(const float4* __restrict__ s0, const float4* __restrict__ s1,
                              const float4* __restrict__ s2, __half* __restrict__ dst)
{
    const int n4 = H_ * H_ / 4;
    int i = blockIdx.x * blockDim.x + threadIdx.x;
    if (i >= 3 * n4) return;
    const int sel = i / n4;
    const int j = i - sel * n4;
    const float4* s = (sel == 0) ? s0 : (sel == 1) ? s1 : s2;
    float4 x = s[j];
    __half h[4];
    h[0] = __float2half(x.x); h[1] = __float2half(x.y);
    h[2] = __float2half(x.z); h[3] = __float2half(x.w);
    *(uint2*)(dst + 4 * (size_t)i) = *(uint2*)h;
}

// merged convert: 4 output-MLP weight mats -> packed fp16 (vec4)
__global__ void cvtW4_kernel(const float4* __restrict__ s0, const float4* __restrict__ s1,
                             const float4* __restrict__ s2, const float4* __restrict__ s3,
                             __half* __restrict__ dst)
{
    const int n0 = S_ * S_ / 4, n1 = 2 * (S_ * S_ / 4);
    const int n2 = n1 + Q_ * S_ / 4, n3 = n1 + 2 * (Q_ * S_ / 4);
    int i = blockIdx.x * blockDim.x + threadIdx.x;
    if (i >= n3) return;
    float4 x;
    if      (i < n0) x = s0[i];
    else if (i < n1) x = s1[i - n0];
    else if (i < n2) x = s2[i - n1];
    else             x = s3[i - n2];
    __half h[4];
    h[0] = __float2half(x.x); h[1] = __float2half(x.y);
    h[2] = __float2half(x.z); h[3] = __float2half(x.w);
    *(uint2*)(dst + 4 * (size_t)i) = *(uint2*)h;
}

// ---------------- fused gate (vectorized x4, fast math) ----------------
__global__ void gate_kernel(const float* __restrict__ prev_y,
                            const float* __restrict__ prev_hidden,
                            const float* __restrict__ coarse,
                            const float* __restrict__ W_Ic,
                            const float* __restrict__ W_If,
                            const float* __restrict__ bias_u,
                            const float* __restrict__ bias_r,
                            const float* __restrict__ bias_e,
                            const float* __restrict__ Rbuf,
                            float* __restrict__ hidden_out,
                            __half* __restrict__ hid_hi,
                            __half* __restrict__ hid_lo)
{
    const int HV = H_ / 4;
    int v = blockIdx.x * blockDim.x + threadIdx.x;
    if (v >= B_ * HV) return;
    int b = v / HV;
    int j = (v - b * HV) * 4;
    size_t idx = (size_t)b * H_ + j;
    const size_t NBH = (size_t)B_ * H_;

    float py0 = prev_y[2 * b], py1 = prev_y[2 * b + 1];
    float4 Ru4 = *(const float4*)(Rbuf + idx);
    float4 Rr4 = *(const float4*)(Rbuf + NBH + idx);
    float4 Re4 = *(const float4*)(Rbuf + 2 * NBH + idx);
    float4 ph4 = *(const float4*)(prev_hidden + idx);

    float h[4];
    const float* Ru = (const float*)&Ru4;
    const float* Rr = (const float*)&Rr4;
    const float* Re = (const float*)&Re4;
    const float* ph = (const float*)&ph4;

    if (j < S_) {
#pragma unroll
        for (int q = 0; q < 4; ++q) {
            int jj = j + q;
            float Iu = py0 * W_Ic[jj * 2] + py1 * W_Ic[jj * 2 + 1];
            float Ir = py0 * W_Ic[(S_ + jj) * 2] + py1 * W_Ic[(S_ + jj) * 2 + 1];
            float Ie = py0 * W_Ic[(2 * S_ + jj) * 2] + py1 * W_Ic[(2 * S_ + jj) * 2 + 1];
            float u = fsigm(Ru[q] + Iu + bias_u[jj]);
            float r = fsigm(Rr[q] + Ir + bias_r[jj]);
            float e = ftanh(r * Re[q] + Ie + bias_e[jj]);
            h[q] = u * ph[q] + (1.f - u) * e;
        }
    } else {
        float cc = coarse[b];
#pragma unroll
        for (int q = 0; q < 4; ++q) {
            int jj = j + q;
            int jf = jj - S_;
            float Iu = py0 * W_If[jf * 3] + py1 * W_If[jf * 3 + 1] + cc * W_If[jf * 3 + 2];
            float Ir = py0 * W_If[(S_ + jf) * 3] + py1 * W_If[(S_ + jf) * 3 + 1] + cc * W_If[(S_ + jf) * 3 + 2];
            float Ie = py0 * W_If[(2 * S_ + jf) * 3] + py1 * W_If[(2 * S_ + jf) * 3 + 1] + cc * W_If[(2 * S_ + jf) * 3 + 2];
            float u = fsigm(Ru[q] + Iu + bias_u[jj]);
            float r = fsigm(Rr[q] + Ir + bias_r[jj]);
            float e = ftanh(r * Re[q] + Ie + bias_e[jj]);
            h[q] = u * ph[q] + (1.f - u) * e;
        }
    }

    *(float4*)(hidden_out + idx) = make_float4(h[0], h[1], h[2], h[3]);

    __half hh[4], hl[4];
#pragma unroll
    for (int q = 0; q < 4; ++q) {
        __half hi = __float2half(h[q]);
        hh[q] = hi;
        hl[q] = __float2half(h[q] - __half2float(hi));
    }
    *(uint2*)(hid_hi + idx) = *(uint2*)hh;
    *(uint2*)(hid_lo + idx) = *(uint2*)hl;
}

// ---------------- launch ----------------
extern "C" void kernel_launch(void* const* d_in, const int* in_sizes, int n_in,
                              void* d_out, int out_size)
{
    const float* prev_y      = (const float*)d_in[0];
    const float* prev_hidden = (const float*)d_in[1];
    const float* coarse      = (const float*)d_in[2];
    const float* W_Ru        = (const float*)d_in[3];
    const float* W_Rr        = (const float*)d_in[4];
    const float* W_Re        = (const float*)d_in[5];
    const float* W_Ic        = (const float*)d_in[6];
    const float* W_If        = (const float*)d_in[7];
    const float* W_O1        = (const float*)d_in[8];
    const float* b_O1        = (const float*)d_in[9];
    const float* W_O2        = (const float*)d_in[10];
    const float* b_O2        = (const float*)d_in[11];
    const float* W_O3        = (const float*)d_in[12];
    const float* b_O3        = (const float*)d_in[13];
    const float* W_O4        = (const float*)d_in[14];
    const float* b_O4        = (const float*)d_in[15];
    const float* bias_u      = (const float*)d_in[16];
    const float* bias_r      = (const float*)d_in[17];
    const float* bias_e      = (const float*)d_in[18];

    float* out        = (float*)d_out;
    float* out_coarse = out;
    float* hidden     = out + 2 * (size_t)B_ * Q_;

    float* Rbuf; __half *Ah, *Hh, *Hl, *Th, *Tl, *Wh;
    cudaGetSymbolAddress((void**)&Rbuf, g_R);
    cudaGetSymbolAddress((void**)&Ah, g_Ah);
    cudaGetSymbolAddress((void**)&Hh, g_Hh);
    cudaGetSymbolAddress((void**)&Hl, g_Hl);
    cudaGetSymbolAddress((void**)&Th, g_Th);
    cudaGetSymbolAddress((void**)&Tl, g_Tl);
    cudaGetSymbolAddress((void**)&Wh, g_Wh);

    const int SM1 = 5 * 16384;   // 1-term: 5 stages x 16KB
    const int SM2 = 4 * 24576;   // 2-term: 4 stages x 24KB
    cudaFuncSetAttribute(gemm_mma<0, true, 1>,  cudaFuncAttributeMaxDynamicSharedMemorySize, SM1);
    cudaFuncSetAttribute(gemm_mma<2, false, 2>, cudaFuncAttributeMaxDynamicSharedMemorySize, SM2);
    cudaFuncSetAttribute(gemm_mma<1, false, 2>, cudaFuncAttributeMaxDynamicSharedMemorySize, SM2);

    const int NBS = B_ * S_;
    dim3 blk(256);

    // converts (3 launches)
    cvtW_kernel<<<(B_ * H_ / 4 + 255) / 256, 256>>>((const float4*)prev_hidden, Ah, B_ * H_ / 4);
    cvtWR3_kernel<<<(3 * H_ * H_ / 4 + 255) / 256, 256>>>((const float4*)W_Ru, (const float4*)W_Rr,
                                                          (const float4*)W_Re, Wh + OFF_WR);
    cvtW4_kernel<<<((2 * S_ * S_ + 2 * Q_ * S_) / 4 + 255) / 256, 256>>>(
        (const float4*)W_O1, (const float4*)W_O3, (const float4*)W_O2, (const float4*)W_O4,
        Wh + OFF_WO1);

    // fused recurrent projections (1-term fp16), N = 3*H = 2688
    dim3 g1(3 * H_ / 128, B_ / 128, 1);  // (21, 64)
    gemm_mma<0, true, 1><<<g1, blk, SM1>>>(Ah, nullptr, H_, Wh + OFF_WR,
                                           3 * H_, H_, nullptr, nullptr,
                                           Rbuf, nullptr, nullptr, H_, 0, 0, 0);

    // fused gates -> hidden (fp32 to d_out) + fp16 hi/lo pair
    gate_kernel<<<(B_ * (H_ / 4) + 255) / 256, 256>>>(prev_y, prev_hidden, coarse, W_Ic, W_If,
                                                      bias_u, bias_r, bias_e, Rbuf, hidden, Hh, Hl);

    // relu(h_half @ W^T + b) -> fp16 pair scratch; z batches O1 / O3
    dim3 g2((S_ + 127) / 128, B_ / 128, 2);  // (4, 64, 2)
    gemm_mma<2, false, 2><<<g2, blk, SM2>>>(Hh, Hl, H_, Wh + OFF_WO1,
                                            S_, S_, b_O1, b_O3,
                                            nullptr, Th, Tl, S_,
                                            S_, S_ * S_, NBS);

    // logits -> d_out; z batches O2 / O4
    dim3 g3(Q_ / 128, B_ / 128, 2);  // (2, 64, 2)
    gemm_mma<1, false, 2><<<g3, blk, SM2>>>(Th, Tl, S_, Wh + OFF_WO2,
                                            Q_, S_, b_O2, b_O4,
                                            out_coarse, nullptr, nullptr, Q_,
                                            NBS, Q_ * S_, B_ * Q_);
}